// round 13
// baseline (speedup 1.0000x reference)
#include <cuda_runtime.h>
#include <cuda_bf16.h>
#include <cstdint>

#define MAXN 50000
#define MAXE 800000
#define D    128

// ---------------------------------------------------------------------------
// Static device scratch (no allocation allowed)
// ---------------------------------------------------------------------------
__device__ float g_denom[MAXN];        // sum of w into dst
__device__ int   g_deg[MAXN];          // in-degree
__device__ float g_inv[MAXN];          // 1 / (max(denom,1e-12) * max(deg,1))
__device__ int   g_rowptr[MAXN + 1];   // CSR row pointers (by dst)
__device__ int   g_cursor[MAXN];       // scatter cursors
__device__ int2  g_edge[MAXE];         // CSR: {src, coef-bits} packed
__device__ float g_t[MAXN * D];        // combined input (x + agg) per layer
__device__ float g_h[MAXN * D];        // layer-1 output

// ---------------------------------------------------------------------------
// 1. Zero denom/deg
// ---------------------------------------------------------------------------
__global__ void zero_kernel(int n_nodes) {
    int i = blockIdx.x * blockDim.x + threadIdx.x;
    if (i < n_nodes) {
        g_denom[i] = 0.0f;
        g_deg[i]   = 0;
    }
}

// ---------------------------------------------------------------------------
// 2. Histogram: denom[dst] += w, deg[dst] += 1
// ---------------------------------------------------------------------------
__global__ void hist_kernel(const float* __restrict__ w,
                            const int* __restrict__ dst,
                            int n_edges) {
    int e = blockIdx.x * blockDim.x + threadIdx.x;
    if (e >= n_edges) return;
    int d = dst[e];
    atomicAdd(&g_denom[d], w[e]);
    atomicAdd(&g_deg[d], 1);
}

// ---------------------------------------------------------------------------
// 3. Exclusive scan of deg -> rowptr/cursor; fold inv = 1/(denom*deg).
//    Single block, 1024 threads.
// ---------------------------------------------------------------------------
__global__ void __launch_bounds__(1024) scan_kernel(int n_nodes, int n_edges) {
    __shared__ int sh[1024];
    const int tid = threadIdx.x;
    const int CH = (n_nodes + 1023) / 1024;
    const int base = tid * CH;

    int s = 0;
    for (int i = 0; i < CH; i++) {
        int idx = base + i;
        if (idx < n_nodes) s += g_deg[idx];
    }
    sh[tid] = s;
    __syncthreads();

    for (int off = 1; off < 1024; off <<= 1) {
        int t = (tid >= off) ? sh[tid - off] : 0;
        __syncthreads();
        sh[tid] += t;
        __syncthreads();
    }

    int run = sh[tid] - s;
    for (int i = 0; i < CH; i++) {
        int idx = base + i;
        if (idx < n_nodes) {
            g_rowptr[idx] = run;
            g_cursor[idx] = run;
            int dg = g_deg[idx];
            run += dg;
            float dn = fmaxf(g_denom[idx], 1e-12f) * fmaxf((float)dg, 1.0f);
            g_inv[idx] = 1.0f / dn;
        }
    }
    if (tid == 0) g_rowptr[n_nodes] = n_edges;
}

// ---------------------------------------------------------------------------
// 4. Scatter edges into packed CSR: edge = {src, w * inv[dst]}
// ---------------------------------------------------------------------------
__global__ void scatter_kernel(const float* __restrict__ w,
                               const int* __restrict__ src,
                               const int* __restrict__ dst,
                               int n_edges) {
    int e = blockIdx.x * blockDim.x + threadIdx.x;
    if (e >= n_edges) return;
    int d = dst[e];
    int p = atomicAdd(&g_cursor[d], 1);
    float c = w[e] * g_inv[d];
    g_edge[p] = make_int2(src[e], __float_as_int(c));
}

// ---------------------------------------------------------------------------
// 5. Aggregation: warp per node (128-dim), no atomics.
//    tout[v] = xin[v] + sum_{e into v} xin[edge.src] * edge.coef
// ---------------------------------------------------------------------------
__global__ void __launch_bounds__(256) agg_kernel(
    const float* __restrict__ xin,
    float* __restrict__ tout,
    int n_nodes)
{
    int gtid = blockIdx.x * blockDim.x + threadIdx.x;
    int v = gtid >> 5;
    int lane = gtid & 31;
    if (v >= n_nodes) return;

    int beg = g_rowptr[v];
    int end = g_rowptr[v + 1];

    float4 acc = make_float4(0.f, 0.f, 0.f, 0.f);
    int i = beg;
    for (; i + 3 < end; i += 4) {
        int2 e0 = __ldg(&g_edge[i]);
        int2 e1 = __ldg(&g_edge[i + 1]);
        int2 e2 = __ldg(&g_edge[i + 2]);
        int2 e3 = __ldg(&g_edge[i + 3]);
        float4 x0 = __ldg(reinterpret_cast<const float4*>(xin + (size_t)e0.x * D) + lane);
        float4 x1 = __ldg(reinterpret_cast<const float4*>(xin + (size_t)e1.x * D) + lane);
        float4 x2 = __ldg(reinterpret_cast<const float4*>(xin + (size_t)e2.x * D) + lane);
        float4 x3 = __ldg(reinterpret_cast<const float4*>(xin + (size_t)e3.x * D) + lane);
        float c0 = __int_as_float(e0.y);
        float c1 = __int_as_float(e1.y);
        float c2 = __int_as_float(e2.y);
        float c3 = __int_as_float(e3.y);
        acc.x = fmaf(x0.x, c0, acc.x); acc.y = fmaf(x0.y, c0, acc.y);
        acc.z = fmaf(x0.z, c0, acc.z); acc.w = fmaf(x0.w, c0, acc.w);
        acc.x = fmaf(x1.x, c1, acc.x); acc.y = fmaf(x1.y, c1, acc.y);
        acc.z = fmaf(x1.z, c1, acc.z); acc.w = fmaf(x1.w, c1, acc.w);
        acc.x = fmaf(x2.x, c2, acc.x); acc.y = fmaf(x2.y, c2, acc.y);
        acc.z = fmaf(x2.z, c2, acc.z); acc.w = fmaf(x2.w, c2, acc.w);
        acc.x = fmaf(x3.x, c3, acc.x); acc.y = fmaf(x3.y, c3, acc.y);
        acc.z = fmaf(x3.z, c3, acc.z); acc.w = fmaf(x3.w, c3, acc.w);
    }
    for (; i < end; i++) {
        int2 e0 = __ldg(&g_edge[i]);
        float c0 = __int_as_float(e0.y);
        float4 x0 = __ldg(reinterpret_cast<const float4*>(xin + (size_t)e0.x * D) + lane);
        acc.x = fmaf(x0.x, c0, acc.x); acc.y = fmaf(x0.y, c0, acc.y);
        acc.z = fmaf(x0.z, c0, acc.z); acc.w = fmaf(x0.w, c0, acc.w);
    }

    float4 xv = *(reinterpret_cast<const float4*>(xin + (size_t)v * D) + lane);
    acc.x += xv.x; acc.y += xv.y; acc.z += xv.z; acc.w += xv.w;
    *(reinterpret_cast<float4*>(tout + (size_t)v * D) + lane) = acc;
}

// ---------------------------------------------------------------------------
// 6. MLP: out = relu(t @ W^T + b).  W is [DOUT,128] row-major.
//    BM=128 rows, full DOUT cols, BK=32, 256 threads, register tile TM x 8.
// ---------------------------------------------------------------------------
template <int DOUT, int TM>
__global__ void __launch_bounds__(256) mlp_kernel(
    const float* __restrict__ t,
    const float* __restrict__ W,
    const float* __restrict__ bias,
    float* __restrict__ out,
    int N)
{
    constexpr int BM  = 128;
    constexpr int BK  = 32;
    constexpr int NCG = DOUT / 8;
    constexpr int SAP = BM + 4;
    constexpr int SWP = DOUT + 4;

    __shared__ float sAT[BK][SAP];  // [k][row]
    __shared__ float sW [BK][SWP];  // [k][col]

    const int tid = threadIdx.x;
    const int tx = tid % NCG;
    const int ty = tid / NCG;
    const int row0 = blockIdx.x * BM;

    float acc[TM][8];
#pragma unroll
    for (int i = 0; i < TM; i++)
#pragma unroll
        for (int j = 0; j < 8; j++) acc[i][j] = 0.0f;

    for (int kt = 0; kt < D; kt += BK) {
#pragma unroll
        for (int i = 0; i < 4; i++) {
            int idx = tid + i * 256;
            int r = idx >> 3;
            int c4 = idx & 7;
            int grow = row0 + r;
            float4 v = make_float4(0.f, 0.f, 0.f, 0.f);
            if (grow < N)
                v = *reinterpret_cast<const float4*>(t + (size_t)grow * D + kt + c4 * 4);
            sAT[c4 * 4 + 0][r] = v.x;
            sAT[c4 * 4 + 1][r] = v.y;
            sAT[c4 * 4 + 2][r] = v.z;
            sAT[c4 * 4 + 3][r] = v.w;
        }
#pragma unroll
        for (int i = 0; i < DOUT * BK / 256; i++) {
            int idx = tid + i * 256;
            int j  = idx >> 5;
            int kk = idx & 31;
            sW[kk][j] = W[j * D + kt + kk];
        }
        __syncthreads();

#pragma unroll
        for (int kk = 0; kk < BK; kk++) {
            float a[TM];
#pragma unroll
            for (int i = 0; i < TM; i += 4) {
                float4 av = *reinterpret_cast<const float4*>(&sAT[kk][ty * TM + i]);
                a[i + 0] = av.x; a[i + 1] = av.y; a[i + 2] = av.z; a[i + 3] = av.w;
            }
            float4 b0 = *reinterpret_cast<const float4*>(&sW[kk][tx * 8]);
            float4 b1 = *reinterpret_cast<const float4*>(&sW[kk][tx * 8 + 4]);
            float b[8] = {b0.x, b0.y, b0.z, b0.w, b1.x, b1.y, b1.z, b1.w};
#pragma unroll
            for (int i = 0; i < TM; i++)
#pragma unroll
                for (int j = 0; j < 8; j++)
                    acc[i][j] = fmaf(a[i], b[j], acc[i][j]);
        }
        __syncthreads();
    }

    float bi[8];
#pragma unroll
    for (int j = 0; j < 8; j++) bi[j] = bias[tx * 8 + j];

#pragma unroll
    for (int i = 0; i < TM; i++) {
        int grow = row0 + ty * TM + i;
        if (grow < N) {
            float* op = out + (size_t)grow * DOUT + tx * 8;
            float4 o0, o1;
            o0.x = fmaxf(acc[i][0] + bi[0], 0.f);
            o0.y = fmaxf(acc[i][1] + bi[1], 0.f);
            o0.z = fmaxf(acc[i][2] + bi[2], 0.f);
            o0.w = fmaxf(acc[i][3] + bi[3], 0.f);
            o1.x = fmaxf(acc[i][4] + bi[4], 0.f);
            o1.y = fmaxf(acc[i][5] + bi[5], 0.f);
            o1.z = fmaxf(acc[i][6] + bi[6], 0.f);
            o1.w = fmaxf(acc[i][7] + bi[7], 0.f);
            *reinterpret_cast<float4*>(op)     = o0;
            *reinterpret_cast<float4*>(op + 4) = o1;
        }
    }
}

// ---------------------------------------------------------------------------
// Launch (R6 verified ordering: agg -> mlp per layer)
// ---------------------------------------------------------------------------
extern "C" void kernel_launch(void* const* d_in, const int* in_sizes, int n_in,
                              void* d_out, int out_size) {
    const float* x   = (const float*)d_in[0];
    const float* w   = (const float*)d_in[1];
    const float* W1  = (const float*)d_in[2];
    const float* b1  = (const float*)d_in[3];
    const float* W2  = (const float*)d_in[4];
    const float* b2  = (const float*)d_in[5];
    const int*   src = (const int*)d_in[6];
    const int*   dst = (const int*)d_in[7];
    float* out = (float*)d_out;

    const int N = in_sizes[0] / D;   // 50000
    const int E = in_sizes[1];       // 800000

    float* t;  cudaGetSymbolAddress((void**)&t, g_t);
    float* h;  cudaGetSymbolAddress((void**)&h, g_h);

    // CSR build (confirmed-improved version: int2 pack + folded inv)
    zero_kernel<<<(N + 255) / 256, 256>>>(N);
    hist_kernel<<<(E + 255) / 256, 256>>>(w, dst, E);
    scan_kernel<<<1, 1024>>>(N, E);
    scatter_kernel<<<(E + 255) / 256, 256>>>(w, src, dst, E);

    const int aggBlocks = (N * 32 + 255) / 256;

    // Layer 1
    agg_kernel<<<aggBlocks, 256>>>(x, t, N);
    mlp_kernel<128, 8><<<(N + 127) / 128, 256>>>(t, W1, b1, h, N);

    // Layer 2
    agg_kernel<<<aggBlocks, 256>>>(h, t, N);
    mlp_kernel<64, 4><<<(N + 127) / 128, 256>>>(t, W2, b2, out, N);
}

// round 17
// speedup vs baseline: 1.0335x; 1.0335x over previous
#include <cuda_runtime.h>
#include <cuda_bf16.h>
#include <cstdint>

#define MAXN 50000
#define MAXE 800000
#define D    128

// ---------------------------------------------------------------------------
// Static device scratch (no allocation allowed)
// ---------------------------------------------------------------------------
__device__ float g_denom[MAXN];        // sum of w into dst
__device__ int   g_deg[MAXN];          // in-degree
__device__ float g_inv[MAXN];          // 1 / (max(denom,1e-12) * max(deg,1))
__device__ int   g_rowptr[MAXN + 1];   // CSR row pointers (by dst)
__device__ int   g_cursor[MAXN];       // scatter cursors
__device__ int2  g_edge[MAXE];         // CSR: {src, coef-bits} packed
__device__ float g_t[MAXN * D];        // y1 (layer1 GEMM out), then y2
__device__ float g_h[MAXN * D];        // layer-1 output h

// ---------------------------------------------------------------------------
// 1. Zero denom/deg
// ---------------------------------------------------------------------------
__global__ void zero_kernel(int n_nodes) {
    int i = blockIdx.x * blockDim.x + threadIdx.x;
    if (i < n_nodes) {
        g_denom[i] = 0.0f;
        g_deg[i]   = 0;
    }
}

// ---------------------------------------------------------------------------
// 2. Histogram: denom[dst] += w, deg[dst] += 1
// ---------------------------------------------------------------------------
__global__ void hist_kernel(const float* __restrict__ w,
                            const int* __restrict__ dst,
                            int n_edges) {
    int e = blockIdx.x * blockDim.x + threadIdx.x;
    if (e >= n_edges) return;
    int d = dst[e];
    atomicAdd(&g_denom[d], w[e]);
    atomicAdd(&g_deg[d], 1);
}

// ---------------------------------------------------------------------------
// 3. Exclusive scan of deg -> rowptr/cursor; fold inv = 1/(denom*deg).
//    Single block, 1024 threads.
// ---------------------------------------------------------------------------
__global__ void __launch_bounds__(1024) scan_kernel(int n_nodes, int n_edges) {
    __shared__ int sh[1024];
    const int tid = threadIdx.x;
    const int CH = (n_nodes + 1023) / 1024;
    const int base = tid * CH;

    int s = 0;
    for (int i = 0; i < CH; i++) {
        int idx = base + i;
        if (idx < n_nodes) s += g_deg[idx];
    }
    sh[tid] = s;
    __syncthreads();

    for (int off = 1; off < 1024; off <<= 1) {
        int t = (tid >= off) ? sh[tid - off] : 0;
        __syncthreads();
        sh[tid] += t;
        __syncthreads();
    }

    int run = sh[tid] - s;
    for (int i = 0; i < CH; i++) {
        int idx = base + i;
        if (idx < n_nodes) {
            g_rowptr[idx] = run;
            g_cursor[idx] = run;
            int dg = g_deg[idx];
            run += dg;
            float dn = fmaxf(g_denom[idx], 1e-12f) * fmaxf((float)dg, 1.0f);
            g_inv[idx] = 1.0f / dn;
        }
    }
    if (tid == 0) g_rowptr[n_nodes] = n_edges;
}

// ---------------------------------------------------------------------------
// 4. Scatter edges into packed CSR: edge = {src, w * inv[dst]}
// ---------------------------------------------------------------------------
__global__ void scatter_kernel(const float* __restrict__ w,
                               const int* __restrict__ src,
                               const int* __restrict__ dst,
                               int n_edges) {
    int e = blockIdx.x * blockDim.x + threadIdx.x;
    if (e >= n_edges) return;
    int d = dst[e];
    int p = atomicAdd(&g_cursor[d], 1);
    float c = w[e] * g_inv[d];
    g_edge[p] = make_int2(src[e], __float_as_int(c));
}

// ---------------------------------------------------------------------------
// 5a. Aggregation + bias + relu, 128-dim: warp per node, lane = float4.
//     out[v] = relu(y[v] + sum_e y[src_e]*coef_e + bias)
// ---------------------------------------------------------------------------
__global__ void __launch_bounds__(256) aggrelu128_kernel(
    const float* __restrict__ y,
    const float* __restrict__ bias,
    float* __restrict__ out,
    int n_nodes)
{
    int gtid = blockIdx.x * blockDim.x + threadIdx.x;
    int v = gtid >> 5;
    int lane = gtid & 31;
    if (v >= n_nodes) return;

    int beg = g_rowptr[v];
    int end = g_rowptr[v + 1];

    float4 acc = make_float4(0.f, 0.f, 0.f, 0.f);
    int i = beg;
    for (; i + 3 < end; i += 4) {
        int2 e0 = __ldg(&g_edge[i]);
        int2 e1 = __ldg(&g_edge[i + 1]);
        int2 e2 = __ldg(&g_edge[i + 2]);
        int2 e3 = __ldg(&g_edge[i + 3]);
        float4 x0 = __ldg(reinterpret_cast<const float4*>(y + (size_t)e0.x * 128) + lane);
        float4 x1 = __ldg(reinterpret_cast<const float4*>(y + (size_t)e1.x * 128) + lane);
        float4 x2 = __ldg(reinterpret_cast<const float4*>(y + (size_t)e2.x * 128) + lane);
        float4 x3 = __ldg(reinterpret_cast<const float4*>(y + (size_t)e3.x * 128) + lane);
        float c0 = __int_as_float(e0.y);
        float c1 = __int_as_float(e1.y);
        float c2 = __int_as_float(e2.y);
        float c3 = __int_as_float(e3.y);
        acc.x = fmaf(x0.x, c0, acc.x); acc.y = fmaf(x0.y, c0, acc.y);
        acc.z = fmaf(x0.z, c0, acc.z); acc.w = fmaf(x0.w, c0, acc.w);
        acc.x = fmaf(x1.x, c1, acc.x); acc.y = fmaf(x1.y, c1, acc.y);
        acc.z = fmaf(x1.z, c1, acc.z); acc.w = fmaf(x1.w, c1, acc.w);
        acc.x = fmaf(x2.x, c2, acc.x); acc.y = fmaf(x2.y, c2, acc.y);
        acc.z = fmaf(x2.z, c2, acc.z); acc.w = fmaf(x2.w, c2, acc.w);
        acc.x = fmaf(x3.x, c3, acc.x); acc.y = fmaf(x3.y, c3, acc.y);
        acc.z = fmaf(x3.z, c3, acc.z); acc.w = fmaf(x3.w, c3, acc.w);
    }
    for (; i < end; i++) {
        int2 e0 = __ldg(&g_edge[i]);
        float c0 = __int_as_float(e0.y);
        float4 x0 = __ldg(reinterpret_cast<const float4*>(y + (size_t)e0.x * 128) + lane);
        acc.x = fmaf(x0.x, c0, acc.x); acc.y = fmaf(x0.y, c0, acc.y);
        acc.z = fmaf(x0.z, c0, acc.z); acc.w = fmaf(x0.w, c0, acc.w);
    }

    float4 yv = *(reinterpret_cast<const float4*>(y + (size_t)v * 128) + lane);
    float4 bv = *(reinterpret_cast<const float4*>(bias) + lane);
    float4 o;
    o.x = fmaxf(acc.x + yv.x + bv.x, 0.f);
    o.y = fmaxf(acc.y + yv.y + bv.y, 0.f);
    o.z = fmaxf(acc.z + yv.z + bv.z, 0.f);
    o.w = fmaxf(acc.w + yv.w + bv.w, 0.f);
    *(reinterpret_cast<float4*>(out + (size_t)v * 128) + lane) = o;
}

// ---------------------------------------------------------------------------
// 5b. Aggregation + bias + relu, 64-dim: warp per node, lane = float2.
//     Full warp per gather (256B row), no intra-warp divergence.
// ---------------------------------------------------------------------------
__global__ void __launch_bounds__(256) aggrelu64_kernel(
    const float* __restrict__ y,
    const float* __restrict__ bias,
    float* __restrict__ out,
    int n_nodes)
{
    int gtid = blockIdx.x * blockDim.x + threadIdx.x;
    int v = gtid >> 5;
    int lane = gtid & 31;
    if (v >= n_nodes) return;

    int beg = g_rowptr[v];
    int end = g_rowptr[v + 1];

    float2 acc = make_float2(0.f, 0.f);
    int i = beg;
    for (; i + 3 < end; i += 4) {
        int2 e0 = __ldg(&g_edge[i]);
        int2 e1 = __ldg(&g_edge[i + 1]);
        int2 e2 = __ldg(&g_edge[i + 2]);
        int2 e3 = __ldg(&g_edge[i + 3]);
        float2 x0 = __ldg(reinterpret_cast<const float2*>(y + (size_t)e0.x * 64) + lane);
        float2 x1 = __ldg(reinterpret_cast<const float2*>(y + (size_t)e1.x * 64) + lane);
        float2 x2 = __ldg(reinterpret_cast<const float2*>(y + (size_t)e2.x * 64) + lane);
        float2 x3 = __ldg(reinterpret_cast<const float2*>(y + (size_t)e3.x * 64) + lane);
        float c0 = __int_as_float(e0.y);
        float c1 = __int_as_float(e1.y);
        float c2 = __int_as_float(e2.y);
        float c3 = __int_as_float(e3.y);
        acc.x = fmaf(x0.x, c0, acc.x); acc.y = fmaf(x0.y, c0, acc.y);
        acc.x = fmaf(x1.x, c1, acc.x); acc.y = fmaf(x1.y, c1, acc.y);
        acc.x = fmaf(x2.x, c2, acc.x); acc.y = fmaf(x2.y, c2, acc.y);
        acc.x = fmaf(x3.x, c3, acc.x); acc.y = fmaf(x3.y, c3, acc.y);
    }
    for (; i < end; i++) {
        int2 e0 = __ldg(&g_edge[i]);
        float c0 = __int_as_float(e0.y);
        float2 x0 = __ldg(reinterpret_cast<const float2*>(y + (size_t)e0.x * 64) + lane);
        acc.x = fmaf(x0.x, c0, acc.x); acc.y = fmaf(x0.y, c0, acc.y);
    }

    float2 yv = *(reinterpret_cast<const float2*>(y + (size_t)v * 64) + lane);
    float2 bv = *(reinterpret_cast<const float2*>(bias) + lane);
    float2 o;
    o.x = fmaxf(acc.x + yv.x + bv.x, 0.f);
    o.y = fmaxf(acc.y + yv.y + bv.y, 0.f);
    *(reinterpret_cast<float2*>(out + (size_t)v * 64) + lane) = o;
}

// ---------------------------------------------------------------------------
// 6. Plain GEMM: y = t @ W^T   (W is [DOUT,128] row-major; no bias/activation)
//    BM=128 rows, full DOUT cols, BK=32, 256 threads, register tile TM x 8.
// ---------------------------------------------------------------------------
template <int DOUT, int TM>
__global__ void __launch_bounds__(256) gemm_kernel(
    const float* __restrict__ t,
    const float* __restrict__ W,
    float* __restrict__ y,
    int N)
{
    constexpr int BM  = 128;
    constexpr int BK  = 32;
    constexpr int NCG = DOUT / 8;
    constexpr int SAP = BM + 4;
    constexpr int SWP = DOUT + 4;

    __shared__ float sAT[BK][SAP];  // [k][row]
    __shared__ float sW [BK][SWP];  // [k][col]

    const int tid = threadIdx.x;
    const int tx = tid % NCG;
    const int ty = tid / NCG;
    const int row0 = blockIdx.x * BM;

    float acc[TM][8];
#pragma unroll
    for (int i = 0; i < TM; i++)
#pragma unroll
        for (int j = 0; j < 8; j++) acc[i][j] = 0.0f;

    for (int kt = 0; kt < D; kt += BK) {
#pragma unroll
        for (int i = 0; i < 4; i++) {
            int idx = tid + i * 256;
            int r = idx >> 3;
            int c4 = idx & 7;
            int grow = row0 + r;
            float4 v = make_float4(0.f, 0.f, 0.f, 0.f);
            if (grow < N)
                v = *reinterpret_cast<const float4*>(t + (size_t)grow * D + kt + c4 * 4);
            sAT[c4 * 4 + 0][r] = v.x;
            sAT[c4 * 4 + 1][r] = v.y;
            sAT[c4 * 4 + 2][r] = v.z;
            sAT[c4 * 4 + 3][r] = v.w;
        }
#pragma unroll
        for (int i = 0; i < DOUT * BK / 256; i++) {
            int idx = tid + i * 256;
            int j  = idx >> 5;
            int kk = idx & 31;
            sW[kk][j] = W[j * D + kt + kk];
        }
        __syncthreads();

#pragma unroll
        for (int kk = 0; kk < BK; kk++) {
            float a[TM];
#pragma unroll
            for (int i = 0; i < TM; i += 4) {
                float4 av = *reinterpret_cast<const float4*>(&sAT[kk][ty * TM + i]);
                a[i + 0] = av.x; a[i + 1] = av.y; a[i + 2] = av.z; a[i + 3] = av.w;
            }
            float4 b0 = *reinterpret_cast<const float4*>(&sW[kk][tx * 8]);
            float4 b1 = *reinterpret_cast<const float4*>(&sW[kk][tx * 8 + 4]);
            float b[8] = {b0.x, b0.y, b0.z, b0.w, b1.x, b1.y, b1.z, b1.w};
#pragma unroll
            for (int i = 0; i < TM; i++)
#pragma unroll
                for (int j = 0; j < 8; j++)
                    acc[i][j] = fmaf(a[i], b[j], acc[i][j]);
        }
        __syncthreads();
    }

#pragma unroll
    for (int i = 0; i < TM; i++) {
        int grow = row0 + ty * TM + i;
        if (grow < N) {
            float* op = y + (size_t)grow * DOUT + tx * 8;
            *reinterpret_cast<float4*>(op) =
                make_float4(acc[i][0], acc[i][1], acc[i][2], acc[i][3]);
            *reinterpret_cast<float4*>(op + 4) =
                make_float4(acc[i][4], acc[i][5], acc[i][6], acc[i][7]);
        }
    }
}

// ---------------------------------------------------------------------------
// Launch (linearity-swap ordering):
//   CSR build -> y1 = x@W1^T -> h = relu(y1 + A y1 + b1)
//             -> y2 = h@W2^T -> out = relu(y2 + A y2 + b2)   [64-dim gathers]
// ---------------------------------------------------------------------------
extern "C" void kernel_launch(void* const* d_in, const int* in_sizes, int n_in,
                              void* d_out, int out_size) {
    const float* x   = (const float*)d_in[0];
    const float* w   = (const float*)d_in[1];
    const float* W1  = (const float*)d_in[2];
    const float* b1  = (const float*)d_in[3];
    const float* W2  = (const float*)d_in[4];
    const float* b2  = (const float*)d_in[5];
    const int*   src = (const int*)d_in[6];
    const int*   dst = (const int*)d_in[7];
    float* out = (float*)d_out;

    const int N = in_sizes[0] / D;   // 50000
    const int E = in_sizes[1];       // 800000

    float* t;  cudaGetSymbolAddress((void**)&t, g_t);
    float* h;  cudaGetSymbolAddress((void**)&h, g_h);

    // CSR build
    zero_kernel<<<(N + 255) / 256, 256>>>(N);
    hist_kernel<<<(E + 255) / 256, 256>>>(w, dst, E);
    scan_kernel<<<1, 1024>>>(N, E);
    scatter_kernel<<<(E + 255) / 256, 256>>>(w, src, dst, E);

    const int aggBlocks = (N * 32 + 255) / 256;

    // Layer 1: GEMM then aggregate (128-dim)
    gemm_kernel<128, 8><<<(N + 127) / 128, 256>>>(x, W1, t, N);
    aggrelu128_kernel<<<aggBlocks, 256>>>(t, b1, h, N);

    // Layer 2: GEMM then aggregate (64-dim, warp-per-node float2)
    gemm_kernel<64, 4><<<(N + 127) / 128, 256>>>(h, W2, t, N);
    aggrelu64_kernel<<<aggBlocks, 256>>>(t, b2, out, N);
}